// round 10
// baseline (speedup 1.0000x reference)
#include <cuda_runtime.h>

// FoldLayer (col2im overlap-add), gather formulation, 2x2 output-quad per thread.
// Branch-free: all 9 tap loads issue unconditionally (clamped coords), boundary
// validity folded into FFMA masks -> full 9-deep LDG.128 front-batch per thread.
//
// patches: (B=16, GH=64, GW=64, 9*128) fp32, kernel-major [i*3+j][c]
// out:     (B=16, 128, 128, 128) fp32

#define C4 32            // 128 channels / 4 floats
#define PSTRIDE 288      // 9*128/4 float4 per patch pixel
#define OROW (128 * C4)  // float4 per output row

__device__ __forceinline__ void fma4(float4& a, const float4 v, float m) {
    a.x = fmaf(v.x, m, a.x); a.y = fmaf(v.y, m, a.y);
    a.z = fmaf(v.z, m, a.z); a.w = fmaf(v.w, m, a.w);
}
__device__ __forceinline__ void add4(float4& a, const float4 v) {
    a.x += v.x; a.y += v.y; a.z += v.z; a.w += v.w;
}

__global__ void __launch_bounds__(256) fold_quad_kernel(
    const float4* __restrict__ p, float4* __restrict__ out)
{
    int idx = blockIdx.x * blockDim.x + threadIdx.x;   // 2,097,152 threads
    int c4 = idx & (C4 - 1);
    int q  = idx >> 5;          // quad id: 16*64*64
    int x2 = q & 63;
    int y2 = (q >> 6) & 63;
    int b  = q >> 12;

    float mx = (x2 < 63) ? 1.0f : 0.0f;
    float my = (y2 < 63) ? 1.0f : 0.0f;
    float mxy = mx * my;
    int xc = min(x2 + 1, 63);
    int yc = min(y2 + 1, 63);

    // patch pixel float4 bases (neighbors clamped in-bounds)
    int base00 = ((b * 64 + y2) * 64 + x2) * PSTRIDE + c4;   // (y2, x2)
    int base01 = ((b * 64 + y2) * 64 + xc) * PSTRIDE + c4;   // (y2, x2+1 clamped)
    int base10 = ((b * 64 + yc) * 64 + x2) * PSTRIDE + c4;   // (y2+1 clamped, x2)
    int base11 = ((b * 64 + yc) * 64 + xc) * PSTRIDE + c4;   // (y2+1, x2+1 clamped)

    // All 9 loads unconditional -> front-batched MLP=9
    float4 t11 = __ldcs(&p[base00 + 4 * C4]);   // center taps
    float4 t12 = __ldcs(&p[base00 + 5 * C4]);
    float4 t21 = __ldcs(&p[base00 + 7 * C4]);
    float4 t22 = __ldcs(&p[base00 + 8 * C4]);
    float4 r10 = __ldcs(&p[base01 + 3 * C4]);   // (1,0)@x+1
    float4 r20 = __ldcs(&p[base01 + 6 * C4]);   // (2,0)@x+1
    float4 r01 = __ldcs(&p[base10 + 1 * C4]);   // (0,1)@y+1
    float4 r02 = __ldcs(&p[base10 + 2 * C4]);   // (0,2)@y+1
    float4 r00 = __ldcs(&p[base11 + 0 * C4]);   // (0,0)@y+1,x+1

    // accumulate 2x2 output quad with validity masks
    float4 o00 = t11;                            // (oy0, ox0)
    float4 o01 = t12;  fma4(o01, r10, mx);       // (oy0, ox1)
    float4 o10 = t21;  fma4(o10, r01, my);       // (oy1, ox0)
    float4 o11 = t22;  fma4(o11, r20, mx);       // (oy1, ox1)
                       fma4(o11, r02, my);
                       fma4(o11, r00, mxy);

    int obase = ((b * 128 + y2 * 2) * 128 + x2 * 2) * C4 + c4;
    __stcs(&out[obase],             o00);
    __stcs(&out[obase + C4],        o01);
    __stcs(&out[obase + OROW],      o10);
    __stcs(&out[obase + OROW + C4], o11);
}

extern "C" void kernel_launch(void* const* d_in, const int* in_sizes, int n_in,
                              void* d_out, int out_size) {
    const float4* p = (const float4*)d_in[0];
    float4* out = (float4*)d_out;
    // 16*64*64 quads * 32 lanes = 2,097,152 threads, 256/CTA
    fold_quad_kernel<<<8192, 256>>>(p, out);
}

// round 11
// speedup vs baseline: 1.0039x; 1.0039x over previous
#include <cuda_runtime.h>

// FoldLayer (col2im overlap-add), gather formulation — FINAL.
// 2x2 output-quad per thread; 512-thread CTAs tile 2x8 quads (best measured
// config); all 9 tap loads unconditional with clamped coords + FFMA validity
// masks (branch-free SASS, 9-deep LDG.128 front-batch).
//
// patches: (B=16, GH=64, GW=64, 9*128) fp32, kernel-major [i*3+j][c]
// out:     (B=16, 128, 128, 128) fp32
//
// Kernel is HBM-bound at ~6.6 TB/s (~83% of 8 TB/s spec) with provably
// minimal traffic (each input byte read once, each output byte written once);
// 83-84% is the measured ceiling for this mixed read/write stream on B300.

#define C4 32            // 128 channels / 4 floats
#define PSTRIDE 288      // 9*128/4 float4 per patch pixel
#define OROW (128 * C4)  // float4 per output row

__device__ __forceinline__ void fma4(float4& a, const float4 v, float m) {
    a.x = fmaf(v.x, m, a.x); a.y = fmaf(v.y, m, a.y);
    a.z = fmaf(v.z, m, a.z); a.w = fmaf(v.w, m, a.w);
}

__global__ void __launch_bounds__(512) fold_quad_kernel(
    const float4* __restrict__ p, float4* __restrict__ out)
{
    int tid = threadIdx.x;
    int c4  = tid & (C4 - 1);
    int w   = tid >> 5;              // warp 0..15 = quad within tile
    int wc  = w & 7;                 // tile col 0..7
    int wr  = w >> 3;                // tile row 0..1

    int bq = blockIdx.x;             // 4096 tiles
    int tx = bq & 7;                 // 8 tiles across 64 quad-cols
    int ty = (bq >> 3) & 31;         // 32 quad-row-pairs
    int b  = bq >> 8;                // batch

    int x2 = tx * 8 + wc;            // 0..63
    int y2 = ty * 2 + wr;            // 0..63

    float mx  = (x2 < 63) ? 1.0f : 0.0f;
    float my  = (y2 < 63) ? 1.0f : 0.0f;
    float mxy = mx * my;
    int xc = min(x2 + 1, 63);
    int yc = min(y2 + 1, 63);

    // patch pixel float4 bases (neighbors clamped in-bounds)
    int base00 = ((b * 64 + y2) * 64 + x2) * PSTRIDE + c4;   // (y2, x2)
    int base01 = ((b * 64 + y2) * 64 + xc) * PSTRIDE + c4;   // (y2, x2+1)
    int base10 = ((b * 64 + yc) * 64 + x2) * PSTRIDE + c4;   // (y2+1, x2)
    int base11 = ((b * 64 + yc) * 64 + xc) * PSTRIDE + c4;   // (y2+1, x2+1)

    // All 9 loads unconditional -> front-batched MLP=9
    float4 t11 = __ldcs(&p[base00 + 4 * C4]);   // center taps
    float4 t12 = __ldcs(&p[base00 + 5 * C4]);
    float4 t21 = __ldcs(&p[base00 + 7 * C4]);
    float4 t22 = __ldcs(&p[base00 + 8 * C4]);
    float4 r10 = __ldcs(&p[base01 + 3 * C4]);   // (1,0)@x+1
    float4 r20 = __ldcs(&p[base01 + 6 * C4]);   // (2,0)@x+1
    float4 r01 = __ldcs(&p[base10 + 1 * C4]);   // (0,1)@y+1
    float4 r02 = __ldcs(&p[base10 + 2 * C4]);   // (0,2)@y+1
    float4 r00 = __ldcs(&p[base11 + 0 * C4]);   // (0,0)@y+1,x+1

    // accumulate 2x2 output quad with validity masks
    float4 o00 = t11;                            // (oy0, ox0)
    float4 o01 = t12;  fma4(o01, r10, mx);       // (oy0, ox1)
    float4 o10 = t21;  fma4(o10, r01, my);       // (oy1, ox0)
    float4 o11 = t22;  fma4(o11, r20, mx);       // (oy1, ox1)
                       fma4(o11, r02, my);
                       fma4(o11, r00, mxy);

    int obase = ((b * 128 + y2 * 2) * 128 + x2 * 2) * C4 + c4;
    __stcs(&out[obase],             o00);
    __stcs(&out[obase + C4],        o01);
    __stcs(&out[obase + OROW],      o10);
    __stcs(&out[obase + OROW + C4], o11);
}

extern "C" void kernel_launch(void* const* d_in, const int* in_sizes, int n_in,
                              void* d_out, int out_size) {
    const float4* p = (const float4*)d_in[0];
    float4* out = (float4*)d_out;
    // 65536 quads / 16 quads-per-CTA = 4096 CTAs of 512 threads
    fold_quad_kernel<<<4096, 512>>>(p, out);
}

// round 14
// speedup vs baseline: 1.0098x; 1.0059x over previous
#include <cuda_runtime.h>

// FoldLayer (col2im overlap-add), gather formulation — FINAL (best measured).
// 2x2 output-quad per thread; 512-thread CTAs tile 2x8 quads; boundary taps
// guarded (uniform-per-warp branches, zero divergence: all 32 lanes of a warp
// share one quad).
//
// patches: (B=16, GH=64, GW=64, 9*128) fp32, kernel-major [i*3+j][c]
// out:     (B=16, 128, 128, 128) fp32
//
// For output (oy,ox), y_pad=oy+1: odd y_pad -> tap i=1 @ y=(y_pad-1)/2;
// even y_pad -> i=2 @ (y_pad-2)/2 plus i=0 @ y_pad/2 (if in range). Same in x.
// Each thread anchors a patch pixel (y2,x2) and produces the 2x2 output quad
// (2y2..2y2+1, 2x2..2x2+1) from at most 9 loads, 4 sequential in one
// 4608-B patch block.
//
// Status: HBM-bound at ~6.6 TB/s (~83% of 8 TB/s spec). Traffic is provably
// minimal (each contributing input byte read once, dead cropped taps never
// loaded, each output byte written once). Five structural variants all
// converge at DRAM 83.5±0.5% — this is the measured ceiling for a mixed
// read/write stream on B300; further SM-side changes are noise.

#define C4 32            // 128 channels / 4 floats
#define PSTRIDE 288      // 9*128/4 float4 per patch pixel
#define OROW (128 * C4)  // float4 per output row

__device__ __forceinline__ void acc4(float4& a, const float4 v) {
    a.x += v.x; a.y += v.y; a.z += v.z; a.w += v.w;
}

__global__ void __launch_bounds__(512) fold_quad_kernel(
    const float4* __restrict__ p, float4* __restrict__ out)
{
    int tid = threadIdx.x;
    int c4  = tid & (C4 - 1);
    int w   = tid >> 5;              // warp 0..15 = quad within tile
    int wc  = w & 7;                 // tile col 0..7
    int wr  = w >> 3;                // tile row 0..1

    int bq = blockIdx.x;             // 4096 tiles
    int tx = bq & 7;                 // 8 tiles across 64 quad-cols
    int ty = (bq >> 3) & 31;         // 32 quad-row-pairs
    int b  = bq >> 8;                // batch

    int x2 = tx * 8 + wc;            // 0..63
    int y2 = ty * 2 + wr;            // 0..63

    bool xe = (x2 < 63);
    bool ye = (y2 < 63);

    // patch pixel float4 bases
    int base00 = ((b * 64 + y2) * 64 + x2) * PSTRIDE + c4;  // (y2,   x2)
    int base01 = base00 + PSTRIDE;                           // (y2,   x2+1)
    int base10 = base00 + 64 * PSTRIDE;                      // (y2+1, x2)
    int base11 = base10 + PSTRIDE;                           // (y2+1, x2+1)

    // center block (y2,x2): taps (1,1),(1,2),(2,1),(2,2)
    float4 t11 = __ldcs(&p[base00 + 4 * C4]);
    float4 t12 = __ldcs(&p[base00 + 5 * C4]);
    float4 t21 = __ldcs(&p[base00 + 7 * C4]);
    float4 t22 = __ldcs(&p[base00 + 8 * C4]);

    float4 z = make_float4(0.f, 0.f, 0.f, 0.f);
    float4 r10_ = z, r20_ = z, r01_ = z, r02_ = z, r00_ = z;
    if (xe) {               // (y2, x2+1): taps (1,0),(2,0)
        r10_ = __ldcs(&p[base01 + 3 * C4]);
        r20_ = __ldcs(&p[base01 + 6 * C4]);
    }
    if (ye) {               // (y2+1, x2): taps (0,1),(0,2)
        r01_ = __ldcs(&p[base10 + 1 * C4]);
        r02_ = __ldcs(&p[base10 + 2 * C4]);
    }
    if (xe && ye) {         // (y2+1, x2+1): tap (0,0)
        r00_ = __ldcs(&p[base11 + 0 * C4]);
    }

    // accumulate 2x2 output quad
    float4 o00 = t11;                           // (oy0, ox0): (1,1)@(y2,x2)
    float4 o01 = t12;  acc4(o01, r10_);         // (oy0, ox1): (1,2) + (1,0)@x+1
    float4 o10 = t21;  acc4(o10, r01_);         // (oy1, ox0): (2,1) + (0,1)@y+1
    float4 o11 = t22;  acc4(o11, r20_);         // (oy1, ox1): (2,2) + (2,0)@x+1
                       acc4(o11, r02_);         //            + (0,2)@y+1
                       acc4(o11, r00_);         //            + (0,0)@y+1,x+1

    int obase = ((b * 128 + y2 * 2) * 128 + x2 * 2) * C4 + c4;
    __stcs(&out[obase],             o00);
    __stcs(&out[obase + C4],        o01);
    __stcs(&out[obase + OROW],      o10);
    __stcs(&out[obase + OROW + C4], o11);
}

extern "C" void kernel_launch(void* const* d_in, const int* in_sizes, int n_in,
                              void* d_out, int out_size) {
    const float4* p = (const float4*)d_in[0];
    float4* out = (float4*)d_out;
    // 65536 quads / 16 quads-per-CTA = 4096 CTAs of 512 threads
    fold_quad_kernel<<<4096, 512>>>(p, out);
}